// round 9
// baseline (speedup 1.0000x reference)
#include <cuda_runtime.h>
#include <cstdint>

// MessagePassing scatter-add:  out[dst[e], :] += x[src[e], :]
// x: [N, 64] f32, edge_index: [2, E] int32 (harness-narrowed), out: [N, 64] f32.
//
// R8: rank-in-histogram CSR build. The hist atomic's return value IS the
// edge's rank within its dst segment, so the scatter pass needs no atomics:
//   1. hist_rank : rank[e] = atomicAdd(counts[dst[e]], 1)  (rank stored int4)
//   2. scan1     : per-1024-chunk sums -> partials
//   3. scan3     : base from partials + local scan -> offsets; re-zero counts
//   4. scatter   : perm[offsets[dst[e]] + rank[e]] = src[e]   (atomic-free)
//   5. gather    : half-warp per node, int4 perm reads, single out write

static constexpr int D = 64;
static constexpr int CHUNKS = D / 4;          // 16 float4 per row
static constexpr int N_MAX = 100000;
static constexpr long long E_MAX = 1600000;
static constexpr int SCAN_CHUNK = 1024;
static constexpr int SCAN_BLOCKS = (N_MAX + SCAN_CHUNK - 1) / SCAN_CHUNK;  // 98

__device__ int g_counts[N_MAX];               // zero-init; invariant: zero on entry
__device__ int g_offsets[N_MAX + 1];
__device__ int g_partials[SCAN_BLOCKS];
__device__ int g_rank[E_MAX];
__device__ int g_perm[E_MAX];

// ---------- 1. histogram + rank (8 edges/thread, coalesced rank stores) ----
__global__ void __launch_bounds__(256) k_hist_rank(const int* __restrict__ dst,
                                                   long long E) {
    long long q = (long long)blockIdx.x * blockDim.x + threadIdx.x;
    long long e = q * 8;
    if (e + 8 <= E) {
        int4 a = __ldg((const int4*)(dst + e));
        int4 b = __ldg((const int4*)(dst + e + 4));
        int4 ra, rb;
        ra.x = atomicAdd(&g_counts[a.x], 1);
        ra.y = atomicAdd(&g_counts[a.y], 1);
        ra.z = atomicAdd(&g_counts[a.z], 1);
        ra.w = atomicAdd(&g_counts[a.w], 1);
        rb.x = atomicAdd(&g_counts[b.x], 1);
        rb.y = atomicAdd(&g_counts[b.y], 1);
        rb.z = atomicAdd(&g_counts[b.z], 1);
        rb.w = atomicAdd(&g_counts[b.w], 1);
        *(int4*)(g_rank + e) = ra;
        *(int4*)(g_rank + e + 4) = rb;
    } else {
        for (long long i = e; i < E; i++)
            g_rank[i] = atomicAdd(&g_counts[__ldg(&dst[i])], 1);
    }
}

// ---------- 2. per-chunk sums -> g_partials ----------
__global__ void k_scan1(int n) {
    __shared__ int sm[32];
    int base = blockIdx.x * SCAN_CHUNK + threadIdx.x * 4;
    int s = 0;
#pragma unroll
    for (int k = 0; k < 4; k++)
        if (base + k < n) s += g_counts[base + k];
    int lane = threadIdx.x & 31, wid = threadIdx.x >> 5;
#pragma unroll
    for (int o = 16; o > 0; o >>= 1) s += __shfl_down_sync(~0u, s, o);
    if (lane == 0) sm[wid] = s;
    __syncthreads();
    if (wid == 0) {
        s = (lane < (blockDim.x >> 5)) ? sm[lane] : 0;
#pragma unroll
        for (int o = 16; o > 0; o >>= 1) s += __shfl_down_sync(~0u, s, o);
        if (lane == 0) g_partials[blockIdx.x] = s;
    }
}

// ---------- 3. base-scan + local scan -> offsets; re-zero counts ----------
__global__ void k_scan3(int n, int E) {
    __shared__ int sp[SCAN_BLOCKS];
    __shared__ int sm[33];
    int t = threadIdx.x;
    int lane = t & 31, wid = t >> 5;

    if (t < SCAN_BLOCKS) sp[t] = g_partials[t];
    __syncthreads();
    if (t == 0) {
        int run = 0;
        for (int i = 0; i < SCAN_BLOCKS; i++) { int v = sp[i]; sp[i] = run; run += v; }
    }
    __syncthreads();
    int block_base = sp[blockIdx.x];

    int idx0 = blockIdx.x * SCAN_CHUNK + t * 4;
    int v[4];
    int tsum = 0;
#pragma unroll
    for (int k = 0; k < 4; k++) {
        v[k] = (idx0 + k < n) ? g_counts[idx0 + k] : 0;
        tsum += v[k];
    }
#pragma unroll
    for (int k = 0; k < 4; k++)
        if (idx0 + k < n) g_counts[idx0 + k] = 0;   // restore invariant

    int x = tsum;
#pragma unroll
    for (int o = 1; o < 32; o <<= 1) {
        int y = __shfl_up_sync(~0u, x, o);
        if (lane >= o) x += y;
    }
    if (lane == 31) sm[wid] = x;
    __syncthreads();
    if (wid == 0) {
        int w = (lane < (blockDim.x >> 5)) ? sm[lane] : 0;
#pragma unroll
        for (int o = 1; o < 32; o <<= 1) {
            int y = __shfl_up_sync(~0u, w, o);
            if (lane >= o) w += y;
        }
        sm[lane] = w;
    }
    __syncthreads();
    int excl = ((wid == 0) ? 0 : sm[wid - 1]) + (x - tsum);
    int run = block_base + excl;
#pragma unroll
    for (int k = 0; k < 4; k++) {
        if (idx0 + k < n) {
            g_offsets[idx0 + k] = run;
            run += v[k];
        }
    }
    if (blockIdx.x == 0 && t == 0) g_offsets[n] = E;
}

// ---------- 4. atomic-free scatter (8 edges/thread, MLP=8) ----------
__global__ void __launch_bounds__(256) k_scatter(const int* __restrict__ src,
                                                 const int* __restrict__ dst,
                                                 long long E) {
    long long q = (long long)blockIdx.x * blockDim.x + threadIdx.x;
    long long e = q * 8;
    if (e + 8 <= E) {
        int4 da = __ldg((const int4*)(dst + e));
        int4 db = __ldg((const int4*)(dst + e + 4));
        int4 sa = __ldg((const int4*)(src + e));
        int4 sb = __ldg((const int4*)(src + e + 4));
        int4 ra = *(const int4*)(g_rank + e);
        int4 rb = *(const int4*)(g_rank + e + 4);
        int o0 = __ldg(&g_offsets[da.x]);
        int o1 = __ldg(&g_offsets[da.y]);
        int o2 = __ldg(&g_offsets[da.z]);
        int o3 = __ldg(&g_offsets[da.w]);
        int o4 = __ldg(&g_offsets[db.x]);
        int o5 = __ldg(&g_offsets[db.y]);
        int o6 = __ldg(&g_offsets[db.z]);
        int o7 = __ldg(&g_offsets[db.w]);
        g_perm[o0 + ra.x] = sa.x;
        g_perm[o1 + ra.y] = sa.y;
        g_perm[o2 + ra.z] = sa.z;
        g_perm[o3 + ra.w] = sa.w;
        g_perm[o4 + rb.x] = sb.x;
        g_perm[o5 + rb.y] = sb.y;
        g_perm[o6 + rb.z] = sb.z;
        g_perm[o7 + rb.w] = sb.w;
    } else {
        for (long long i = e; i < E; i++) {
            int d = __ldg(&dst[i]);
            g_perm[__ldg(&g_offsets[d]) + g_rank[i]] = __ldg(&src[i]);
        }
    }
}

// ---------- 5. pull gather: half-warp per node, int4 perm reads ----------
__global__ void __launch_bounds__(256) k_gather(const float4* __restrict__ x,
                                                float4* __restrict__ out,
                                                int n) {
    long long t = (long long)blockIdx.x * blockDim.x + threadIdx.x;
    long long node = t >> 4;
    int c = (int)(t & 15);
    if (node >= n) return;

    int beg = __ldg(&g_offsets[node]);
    int end = __ldg(&g_offsets[node + 1]);

    float4 acc = make_float4(0.f, 0.f, 0.f, 0.f);
    int j = beg;
    // scalar head until 16B-aligned
    for (; j < end && (j & 3); j++) {
        int s = __ldg(&g_perm[j]);
        float4 a = __ldg(&x[(long long)s * CHUNKS + c]);
        acc.x += a.x; acc.y += a.y; acc.z += a.z; acc.w += a.w;
    }
    // vectorized body: one broadcast int4 per 4 edges
    for (; j + 4 <= end; j += 4) {
        int4 s4 = __ldg((const int4*)(g_perm + j));
        float4 a = __ldg(&x[(long long)s4.x * CHUNKS + c]);
        float4 b = __ldg(&x[(long long)s4.y * CHUNKS + c]);
        float4 cc = __ldg(&x[(long long)s4.z * CHUNKS + c]);
        float4 d = __ldg(&x[(long long)s4.w * CHUNKS + c]);
        acc.x += a.x + b.x + cc.x + d.x;
        acc.y += a.y + b.y + cc.y + d.y;
        acc.z += a.z + b.z + cc.z + d.z;
        acc.w += a.w + b.w + cc.w + d.w;
    }
    // scalar tail
    for (; j < end; j++) {
        int s = __ldg(&g_perm[j]);
        float4 a = __ldg(&x[(long long)s * CHUNKS + c]);
        acc.x += a.x; acc.y += a.y; acc.z += a.z; acc.w += a.w;
    }
    out[node * CHUNKS + c] = acc;
}

// ---------- fallback scatter path ----------
__global__ void mp_scatter_tail(const float4* __restrict__ x,
                                const int* __restrict__ src,
                                const int* __restrict__ dst,
                                float* __restrict__ out,
                                long long e0, long long E) {
    long long gid = (long long)blockIdx.x * blockDim.x + threadIdx.x;
    long long e = e0 + (gid >> 4);
    if (e >= E) return;
    int c = (int)(gid & 15);
    int s = __ldg(&src[e]);
    int d = __ldg(&dst[e]);
    float4 v = __ldg(&x[(long long)s * CHUNKS + c]);
    float* p = out + (long long)d * D + c * 4;
    asm volatile("red.global.add.v4.f32 [%0], {%1, %2, %3, %4};"
                 :: "l"(p), "f"(v.x), "f"(v.y), "f"(v.z), "f"(v.w)
                 : "memory");
}

extern "C" void kernel_launch(void* const* d_in, const int* in_sizes, int n_in,
                              void* d_out, int out_size) {
    const float4* x = (const float4*)d_in[0];    // [N, 64] f32 as float4[N*16]
    const int* ei = (const int*)d_in[1];         // [2, E] int32
    long long E = (long long)in_sizes[1] / 2;
    const int* src = ei;
    const int* dst = ei + E;
    int N = out_size / D;

    if (E > E_MAX || N > N_MAX) {
        cudaMemsetAsync(d_out, 0, (size_t)out_size * sizeof(float), 0);
        long long items = E * CHUNKS;
        long long blocks = (items + 255) / 256;
        mp_scatter_tail<<<(unsigned)blocks, 256>>>(x, src, dst, (float*)d_out, 0, E);
        return;
    }

    long long octs = (E + 7) / 8;
    int eb = (int)((octs + 255) / 256);

    k_hist_rank<<<eb, 256>>>(dst, E);
    k_scan1<<<SCAN_BLOCKS, 256>>>(N);
    k_scan3<<<SCAN_BLOCKS, 256>>>(N, (int)E);
    k_scatter<<<eb, 256>>>(src, dst, E);

    long long gthreads = (long long)N * CHUNKS;
    k_gather<<<(unsigned)((gthreads + 255) / 256), 256>>>(x, (float4*)d_out, N);
}